// round 1
// baseline (speedup 1.0000x reference)
#include <cuda_runtime.h>
#include <cuda_bf16.h>
#include <math.h>

// ---------------------------------------------------------------------------
// Problem dims (fixed by setup_inputs)
// ---------------------------------------------------------------------------
#define BB     2      // batch
#define NN     2      // N sequences
#define LL     1024   // seq len
#define DM     512    // d_model
#define DI     512    // d_inner
#define DS     16     // d_state
#define DC     4      // d_conv
#define KK     4      // scan directions
#define DTR    32     // dt_rank
#define NF     9      // features per input scalar: silu + 8 spline bases
#define GS     5
#define SO     3

#define M_IN   (BB*NN*LL)          // 4096 rows, in-proj
#define M_XS   (BB*KK*LL)          // 8192 rows, x-proj
#define K_IN   (DM*NF)             // 4608
#define K_OUT  (2*DI*NF)           // 9216
#define O_IN   (2*DI)              // 1024
#define O_X    (DTR + 2*DS)        // 64
#define O_OUT  DM                  // 512

// ---------------------------------------------------------------------------
// Scratch (__device__ globals: allocation-free)
// ---------------------------------------------------------------------------
__device__ float g_F    [M_XS * K_IN];       // feature buffer (also fits 4096xK_OUT)
__device__ float g_Wc   [K_OUT * O_OUT];     // combined big weights (4608x1024 == 9216x512)
__device__ float g_Wcx  [K_IN * O_X];        // combined x-proj weights
__device__ float g_xz   [M_IN * O_IN];       // (B,N,L,1024) = [x | z]
__device__ float g_xs   [M_XS * DI];         // (B,4,L,512)
__device__ float g_xdbl [M_XS * O_X];        // (B,4,L,64) = [dt|B|C]
__device__ float g_delta[M_XS * DI];         // dts then softplus(delta)
__device__ float g_y    [M_XS * DI];         // scan output (incl. +u*D)
__device__ float g_cat  [M_IN * O_IN];       // (B,2,L,1024) = [y_merged | z]
__device__ float g_dtwT [DTR * DI];          // dt_w transposed

// ---------------------------------------------------------------------------
// Helpers
// ---------------------------------------------------------------------------
__device__ __forceinline__ float silu_f(float x) {
    return x / (1.0f + expf(-x));
}
__device__ __forceinline__ float softplus_f(float x) {
    return fmaxf(x, 0.0f) + log1pf(expf(-fabsf(x)));
}

// ---------------------------------------------------------------------------
// Combined KAN weight build:
// Wc[(i*9+0)*O + o]   = bw[o,i]
// Wc[(i*9+1+s)*O + o] = sw[o,i,s] * sc[o,i]
// ---------------------------------------------------------------------------
__global__ void prep_weights(const float* __restrict__ bw,
                             const float* __restrict__ sw,
                             const float* __restrict__ sc,
                             float* __restrict__ Wc, int O, int I) {
    int idx = blockIdx.x * blockDim.x + threadIdx.x;
    if (idx >= O * I) return;
    int o = idx % O;
    int i = idx / O;
    float scv = sc[o * I + i];
    Wc[(i * NF) * O + o] = bw[o * I + i];
#pragma unroll
    for (int s = 0; s < 8; s++)
        Wc[(i * NF + 1 + s) * O + o] = sw[(o * I + i) * 8 + s] * scv;
}

// ---------------------------------------------------------------------------
// Feature expansion: each scalar x -> [silu(x), cubic B-spline bases b0..b7]
// grid g[t] = (t-3)*0.4 - 1,  t = 0..11
// ---------------------------------------------------------------------------
__global__ void features_kernel(const float* __restrict__ src,
                                float* __restrict__ dst, int Mrows, int I) {
    int idx = blockIdx.x * blockDim.x + threadIdx.x;
    if (idx >= Mrows * I) return;
    float x = src[idx];

    float g[12];
#pragma unroll
    for (int t = 0; t < 12; t++) g[t] = (float)(t - 3) * 0.4f - 1.0f;

    float b[11];
#pragma unroll
    for (int t = 0; t < 11; t++)
        b[t] = (x >= g[t] && x < g[t + 1]) ? 1.0f : 0.0f;

    // Cox-de Boor, degrees 1..3
#pragma unroll
    for (int k = 1; k <= SO; k++) {
#pragma unroll
        for (int t = 0; t < 11; t++) {
            if (t < 11 - k) {
                float a1 = (x - g[t]) / (g[t + k] - g[t]);
                float a2 = (g[t + k + 1] - x) / (g[t + k + 1] - g[t + 1]);
                b[t] = a1 * b[t] + a2 * b[t + 1];
            }
        }
    }

    float* out = dst + (size_t)idx * NF;
    out[0] = silu_f(x);
#pragma unroll
    for (int s = 0; s < 8; s++) out[1 + s] = b[s];
}

// ---------------------------------------------------------------------------
// Tiled SGEMM  C(MxN) = A(MxK) * B(KxN), all row-major, dims divisible by tiles
// ---------------------------------------------------------------------------
template <int BM, int BN, int BK, int TM, int TN>
__global__ __launch_bounds__((BM / TM) * (BN / TN))
void sgemm(const float* __restrict__ A, const float* __restrict__ B,
           float* __restrict__ C, int M, int N, int K,
           int lda, int ldb, int ldc) {
    __shared__ float As[BK][BM];
    __shared__ float Bs[BK][BN];
    constexpr int T = (BM / TM) * (BN / TN);
    int tid = threadIdx.x;
    int bm = blockIdx.y * BM;
    int bn = blockIdx.x * BN;
    int tr = tid / (BN / TN);
    int tc = tid % (BN / TN);

    float acc[TM][TN];
#pragma unroll
    for (int i = 0; i < TM; i++)
#pragma unroll
        for (int j = 0; j < TN; j++) acc[i][j] = 0.0f;

    for (int k0 = 0; k0 < K; k0 += BK) {
#pragma unroll
        for (int e = tid; e < BM * BK; e += T) {
            int m = e / BK, kk = e % BK;
            As[kk][m] = A[(size_t)(bm + m) * lda + k0 + kk];
        }
#pragma unroll
        for (int e = tid; e < BK * BN; e += T) {
            int kk = e / BN, n = e % BN;
            Bs[kk][n] = B[(size_t)(k0 + kk) * ldb + bn + n];
        }
        __syncthreads();
#pragma unroll
        for (int kk = 0; kk < BK; kk++) {
            float ra[TM], rb[TN];
#pragma unroll
            for (int i = 0; i < TM; i++) ra[i] = As[kk][tr * TM + i];
#pragma unroll
            for (int j = 0; j < TN; j++) rb[j] = Bs[kk][tc * TN + j];
#pragma unroll
            for (int i = 0; i < TM; i++)
#pragma unroll
                for (int j = 0; j < TN; j++) acc[i][j] += ra[i] * rb[j];
        }
        __syncthreads();
    }
#pragma unroll
    for (int i = 0; i < TM; i++)
#pragma unroll
        for (int j = 0; j < TN; j++)
            C[(size_t)(bm + tr * TM + i) * ldc + bn + tc * TN + j] = acc[i][j];
}

// ---------------------------------------------------------------------------
// Causal depthwise conv (k=4) + bias + SiLU, writes forward + reversed copies
// ---------------------------------------------------------------------------
__global__ void conv_silu_kernel(const float* __restrict__ xz,
                                 const float* __restrict__ cw,
                                 const float* __restrict__ cb,
                                 float* __restrict__ xs) {
    int idx = blockIdx.x * blockDim.x + threadIdx.x;  // over (BN, L, DI)
    if (idx >= BB * NN * LL * DI) return;
    int d = idx % DI;
    int t = (idx / DI) % LL;
    int bn = idx / (DI * LL);          // b*NN + n
    int b = bn / NN, n = bn % NN;

    float w0 = cw[d * DC + 0], w1 = cw[d * DC + 1];
    float w2 = cw[d * DC + 2], w3 = cw[d * DC + 3];

    const float* xr = xz + ((size_t)bn * LL) * O_IN + d;  // x half: cols [0,512)
    float acc = cb[d];
    if (t - 3 >= 0) acc += xr[(size_t)(t - 3) * O_IN] * w0;
    if (t - 2 >= 0) acc += xr[(size_t)(t - 2) * O_IN] * w1;
    if (t - 1 >= 0) acc += xr[(size_t)(t - 1) * O_IN] * w2;
    acc += xr[(size_t)t * O_IN] * w3;
    float v = silu_f(acc);

    // forward dir n, and reversed dir n+2
    xs[((size_t)((b * KK + n) * LL + t)) * DI + d] = v;
    xs[((size_t)((b * KK + 2 + n) * LL + (LL - 1 - t))) * DI + d] = v;
}

// ---------------------------------------------------------------------------
// dt_w transpose (512x32 -> 32x512)
// ---------------------------------------------------------------------------
__global__ void transpose_dtw(const float* __restrict__ dtw, float* __restrict__ out) {
    int idx = blockIdx.x * blockDim.x + threadIdx.x;
    if (idx >= DTR * DI) return;
    int d = idx % DI, j = idx / DI;
    out[j * DI + d] = dtw[d * DTR + j];
}

// ---------------------------------------------------------------------------
// delta = softplus(dts + dt_bias[k]) in place
// ---------------------------------------------------------------------------
__global__ void softplus_bias_kernel(float* __restrict__ delta,
                                     const float* __restrict__ dt_bias) {
    int idx = blockIdx.x * blockDim.x + threadIdx.x;
    if (idx >= M_XS * DI) return;
    int d = idx % DI;
    int r = idx / DI;            // r = (b*4 + k)*L + t
    int k = (r / LL) % KK;
    delta[idx] = softplus_f(delta[idx] + dt_bias[k * DI + d]);
}

// ---------------------------------------------------------------------------
// Selective scan. Block = (b,k,dblk of 128). 512 threads = 128 d x 4 state-
// groups (4 states each). Quad shuffle-reduce for y = sum_n h_n C_n.
// Fuses  y += u * D.
// ---------------------------------------------------------------------------
__global__ __launch_bounds__(512)
void scan_kernel(const float* __restrict__ xs,
                 const float* __restrict__ delta,
                 const float* __restrict__ xdbl,
                 const float* __restrict__ A_logs,
                 const float* __restrict__ Ds,
                 float* __restrict__ y) {
    int bk   = blockIdx.x >> 2;          // b*4 + k  (0..7)
    int dblk = blockIdx.x & 3;
    int tid  = threadIdx.x;
    int dl_  = tid >> 2;                 // 0..127
    int ng   = tid & 3;                  // state group
    int d    = dblk * 128 + dl_;
    int kdir = bk & 3;

    float A[4], h[4];
#pragma unroll
    for (int j = 0; j < 4; j++) {
        A[j] = -expf(A_logs[((size_t)(kdir * DI + d)) * DS + ng * 4 + j]);
        h[j] = 0.0f;
    }
    float Dv = Ds[kdir * DI + d];

    const size_t rowbase = (size_t)bk * LL;
    for (int t = 0; t < LL; t++) {
        size_t r = rowbase + t;
        float dl = delta[r * DI + d];
        float u  = xs[r * DI + d];
        float du = dl * u;
        const float* Bp = xdbl + r * O_X + DTR + ng * 4;
        const float* Cp = Bp + DS;
        float cy = 0.0f;
#pragma unroll
        for (int j = 0; j < 4; j++) {
            float e = __expf(dl * A[j]);
            h[j] = h[j] * e + du * __ldg(&Bp[j]);
            cy += h[j] * __ldg(&Cp[j]);
        }
        cy += __shfl_xor_sync(0xffffffffu, cy, 1);
        cy += __shfl_xor_sync(0xffffffffu, cy, 2);
        if (ng == 0) y[r * DI + d] = cy + u * Dv;
    }
}

// ---------------------------------------------------------------------------
// Merge fwd/bwd scans and concat with z: g_cat (B,2,L,1024)
// ---------------------------------------------------------------------------
__global__ void merge_kernel(const float* __restrict__ y,
                             const float* __restrict__ xz,
                             float* __restrict__ cat) {
    int idx = blockIdx.x * blockDim.x + threadIdx.x;  // over (B,N,L,DI)
    if (idx >= BB * NN * LL * DI) return;
    int d = idx % DI;
    int t = (idx / DI) % LL;
    int bn = idx / (DI * LL);
    int b = bn / NN, n = bn % NN;

    float yf = y[((size_t)((b * KK + n) * LL + t)) * DI + d];
    float yb = y[((size_t)((b * KK + 2 + n) * LL + (LL - 1 - t))) * DI + d];
    size_t row = (size_t)bn * LL + t;
    cat[row * O_IN + d]        = yf + yb;
    cat[row * O_IN + DI + d]   = xz[row * O_IN + DI + d];   // z passthrough
}

// ---------------------------------------------------------------------------
// Launch
// ---------------------------------------------------------------------------
static inline int cdiv(int a, int b) { return (a + b - 1) / b; }

extern "C" void kernel_launch(void* const* d_in, const int* in_sizes, int n_in,
                              void* d_out, int out_size) {
    const float* hs      = (const float*)d_in[0];
    const float* in_bw   = (const float*)d_in[1];
    const float* in_sw   = (const float*)d_in[2];
    const float* in_sc   = (const float*)d_in[3];
    const float* conv_w  = (const float*)d_in[4];
    const float* conv_b  = (const float*)d_in[5];
    const float* x_bw    = (const float*)d_in[6];
    const float* x_sw    = (const float*)d_in[7];
    const float* x_sc    = (const float*)d_in[8];
    const float* dt_w    = (const float*)d_in[9];
    const float* dt_bias = (const float*)d_in[10];
    const float* A_logs  = (const float*)d_in[11];
    const float* Ds      = (const float*)d_in[12];
    const float* out_bw  = (const float*)d_in[13];
    const float* out_sw  = (const float*)d_in[14];
    const float* out_sc  = (const float*)d_in[15];
    float* out = (float*)d_out;

    float *F, *Wc, *Wcx, *xz, *xs, *xdbl, *delta, *yb, *cat, *dtwT;
    cudaGetSymbolAddress((void**)&F,     g_F);
    cudaGetSymbolAddress((void**)&Wc,    g_Wc);
    cudaGetSymbolAddress((void**)&Wcx,   g_Wcx);
    cudaGetSymbolAddress((void**)&xz,    g_xz);
    cudaGetSymbolAddress((void**)&xs,    g_xs);
    cudaGetSymbolAddress((void**)&xdbl,  g_xdbl);
    cudaGetSymbolAddress((void**)&delta, g_delta);
    cudaGetSymbolAddress((void**)&yb,    g_y);
    cudaGetSymbolAddress((void**)&cat,   g_cat);
    cudaGetSymbolAddress((void**)&dtwT,  g_dtwT);

    const int TPB = 256;

    // ---- in-proj KAN: xz = KAN(hidden_states) ----
    prep_weights<<<cdiv(O_IN * DM, TPB), TPB>>>(in_bw, in_sw, in_sc, Wc, O_IN, DM);
    features_kernel<<<cdiv(M_IN * DM, TPB), TPB>>>(hs, F, M_IN, DM);
    {
        dim3 grid(O_IN / 128, M_IN / 128);
        sgemm<128, 128, 8, 8, 8><<<grid, 256>>>(F, Wc, xz, M_IN, O_IN, K_IN,
                                                K_IN, O_IN, O_IN);
    }

    // ---- conv + silu -> xs (fwd + reversed) ----
    conv_silu_kernel<<<cdiv(BB * NN * LL * DI, TPB), TPB>>>(xz, conv_w, conv_b, xs);

    // ---- x-proj KAN: x_dbl = KAN(xs) ----
    prep_weights<<<cdiv(O_X * DI, TPB), TPB>>>(x_bw, x_sw, x_sc, Wcx, O_X, DI);
    features_kernel<<<cdiv(M_XS * DI, TPB), TPB>>>(xs, F, M_XS, DI);
    {
        dim3 grid(O_X / 64, M_XS / 64);
        sgemm<64, 64, 8, 4, 4><<<grid, 256>>>(F, Wcx, xdbl, M_XS, O_X, K_IN,
                                              K_IN, O_X, O_X);
    }

    // ---- dts = dt @ dt_w^T ; delta = softplus(dts + bias) ----
    transpose_dtw<<<cdiv(DTR * DI, TPB), TPB>>>(dt_w, dtwT);
    {
        dim3 grid(DI / 128, M_XS / 128);
        sgemm<128, 128, 8, 8, 8><<<grid, 256>>>(xdbl, dtwT, delta, M_XS, DI, DTR,
                                                O_X, DI, DI);
    }
    softplus_bias_kernel<<<cdiv(M_XS * DI, TPB), TPB>>>(delta, dt_bias);

    // ---- selective scan (+ u*D) ----
    scan_kernel<<<32, 512>>>(xs, delta, xdbl, A_logs, Ds, yb);

    // ---- merge fwd/bwd, concat z ----
    merge_kernel<<<cdiv(BB * NN * LL * DI, TPB), TPB>>>(yb, xz, cat);

    // ---- out-proj KAN: out = KAN(cat) ----
    prep_weights<<<cdiv(O_OUT * O_IN, TPB), TPB>>>(out_bw, out_sw, out_sc, Wc, O_OUT, O_IN);
    features_kernel<<<cdiv(M_IN * O_IN, TPB), TPB>>>(cat, F, M_IN, O_IN);
    {
        dim3 grid(O_OUT / 128, M_IN / 128);
        sgemm<128, 128, 8, 8, 8><<<grid, 256>>>(F, Wc, out, M_IN, O_OUT, K_OUT,
                                                K_OUT, O_OUT, O_OUT);
    }
}

// round 2
// speedup vs baseline: 2.3243x; 2.3243x over previous
#include <cuda_runtime.h>
#include <cuda_bf16.h>
#include <math.h>

// ---------------------------------------------------------------------------
// Problem dims (fixed by setup_inputs)
// ---------------------------------------------------------------------------
#define BB     2      // batch
#define NN     2      // N sequences
#define LL     1024   // seq len
#define DM     512    // d_model
#define DI     512    // d_inner
#define DS     16     // d_state
#define DC     4      // d_conv
#define KK     4      // scan directions
#define DTR    32     // dt_rank
#define NF     9      // features per input scalar: silu + 8 spline bases
#define GS     5
#define SO     3

#define M_IN   (BB*NN*LL)          // 4096 rows, in-proj
#define M_XS   (BB*KK*LL)          // 8192 rows, x-proj
#define K_IN   (DM*NF)             // 4608
#define K_OUT  (2*DI*NF)           // 9216
#define O_IN   (2*DI)              // 1024
#define O_X    (DTR + 2*DS)        // 64
#define O_OUT  DM                  // 512

// ---------------------------------------------------------------------------
// Scratch (__device__ globals: allocation-free)
// ---------------------------------------------------------------------------
__device__ float g_F    [M_XS * K_IN];       // feature buffer (also fits 4096xK_OUT)
__device__ float g_Wc   [K_OUT * O_OUT];     // combined big weights (4608x1024 == 9216x512)
__device__ float g_Wcx  [K_IN * O_X];        // combined x-proj weights
__device__ float g_xz   [M_IN * O_IN];       // (B,N,L,1024) = [x | z]
__device__ float g_xs   [M_XS * DI];         // (B,4,L,512)
__device__ float g_xdbl [M_XS * O_X];        // (B,4,L,64) = [dt|B|C]
__device__ float g_delta[M_XS * DI];         // dts then softplus(delta)
__device__ float g_y    [M_XS * DI];         // scan output (incl. +u*D)
__device__ float g_cat  [M_IN * O_IN];       // (B,2,L,1024) = [y_merged | z]
__device__ float g_dtwT [DTR * DI];          // dt_w transposed

// ---------------------------------------------------------------------------
// Helpers
// ---------------------------------------------------------------------------
__device__ __forceinline__ float silu_f(float x) {
    return x / (1.0f + expf(-x));
}
__device__ __forceinline__ float softplus_f(float x) {
    return fmaxf(x, 0.0f) + log1pf(expf(-fabsf(x)));
}
__device__ __forceinline__ unsigned f2tf32(float x) {
    unsigned r;
    asm("cvt.rna.tf32.f32 %0, %1;" : "=r"(r) : "f"(x));
    return r;
}

// ---------------------------------------------------------------------------
// Combined KAN weight build:
// Wc[(i*9+0)*O + o]   = bw[o,i]
// Wc[(i*9+1+s)*O + o] = sw[o,i,s] * sc[o,i]
// ---------------------------------------------------------------------------
__global__ void prep_weights(const float* __restrict__ bw,
                             const float* __restrict__ sw,
                             const float* __restrict__ sc,
                             float* __restrict__ Wc, int O, int I) {
    int idx = blockIdx.x * blockDim.x + threadIdx.x;
    if (idx >= O * I) return;
    int o = idx % O;
    int i = idx / O;
    float scv = sc[o * I + i];
    Wc[(i * NF) * O + o] = bw[o * I + i];
#pragma unroll
    for (int s = 0; s < 8; s++)
        Wc[(i * NF + 1 + s) * O + o] = sw[(o * I + i) * 8 + s] * scv;
}

// ---------------------------------------------------------------------------
// Feature expansion: each scalar x -> [silu(x), cubic B-spline bases b0..b7]
// grid g[t] = (t-3)*0.4 - 1,  t = 0..11
// ---------------------------------------------------------------------------
__global__ void features_kernel(const float* __restrict__ src,
                                float* __restrict__ dst, int Mrows, int I) {
    int idx = blockIdx.x * blockDim.x + threadIdx.x;
    if (idx >= Mrows * I) return;
    float x = src[idx];

    float g[12];
#pragma unroll
    for (int t = 0; t < 12; t++) g[t] = (float)(t - 3) * 0.4f - 1.0f;

    float b[11];
#pragma unroll
    for (int t = 0; t < 11; t++)
        b[t] = (x >= g[t] && x < g[t + 1]) ? 1.0f : 0.0f;

#pragma unroll
    for (int k = 1; k <= SO; k++) {
#pragma unroll
        for (int t = 0; t < 11; t++) {
            if (t < 11 - k) {
                float a1 = (x - g[t]) / (g[t + k] - g[t]);
                float a2 = (g[t + k + 1] - x) / (g[t + k + 1] - g[t + 1]);
                b[t] = a1 * b[t] + a2 * b[t + 1];
            }
        }
    }

    float* out = dst + (size_t)idx * NF;
    out[0] = silu_f(x);
#pragma unroll
    for (int s = 0; s < 8; s++) out[1 + s] = b[s];
}

// ---------------------------------------------------------------------------
// TF32 tensor-core GEMM  C(MxN) = A(MxK) * B(KxN), row-major.
// mma.sync.aligned.m16n8k8.tf32, 256 threads = 8 warps, double-buffered
// cp.async pipeline. All dims divisible by tile sizes (asserted by call sites).
// ---------------------------------------------------------------------------
template <int BM, int BN, int BK, int WARPS_M, int WARPS_N>
__global__ __launch_bounds__(256)
void tf32_gemm(const float* __restrict__ A, const float* __restrict__ B,
               float* __restrict__ C, int M, int N, int K,
               int lda, int ldb, int ldc) {
    constexpr int WM = BM / WARPS_M;    // rows per warp
    constexpr int WN = BN / WARPS_N;    // cols per warp
    constexpr int MT = WM / 16;         // m16 tiles per warp
    constexpr int NT = WN / 8;          // n8 tiles per warp
    constexpr int ASTR = BK + 4;
    constexpr int BSTR = BN + 4;

    __shared__ float As[2][BM][ASTR];
    __shared__ float Bs[2][BK][BSTR];

    const int tid  = threadIdx.x;
    const int wid  = tid >> 5;
    const int lane = tid & 31;
    const int wm   = wid / WARPS_N;
    const int wn   = wid % WARPS_N;
    const int g    = lane >> 2;         // group id 0..7
    const int t4   = lane & 3;          // thread in group

    const int bm0 = blockIdx.y * BM;
    const int bn0 = blockIdx.x * BN;

    float acc[MT][NT][4];
#pragma unroll
    for (int i = 0; i < MT; i++)
#pragma unroll
        for (int j = 0; j < NT; j++)
#pragma unroll
            for (int r = 0; r < 4; r++) acc[i][j][r] = 0.0f;

    auto load_tile = [&](int buf, int k0) {
        constexpr int ACH = BM * BK / 4;
#pragma unroll 4
        for (int c = tid; c < ACH; c += 256) {
            int r = c / (BK / 4), cc = c % (BK / 4);
            const float* src = A + (size_t)(bm0 + r) * lda + k0 + cc * 4;
            unsigned dst = (unsigned)__cvta_generic_to_shared(&As[buf][r][cc * 4]);
            asm volatile("cp.async.cg.shared.global [%0], [%1], 16;" ::
                         "r"(dst), "l"(src));
        }
        constexpr int BCH = BK * BN / 4;
#pragma unroll 4
        for (int c = tid; c < BCH; c += 256) {
            int r = c / (BN / 4), cc = c % (BN / 4);
            const float* src = B + (size_t)(k0 + r) * ldb + bn0 + cc * 4;
            unsigned dst = (unsigned)__cvta_generic_to_shared(&Bs[buf][r][cc * 4]);
            asm volatile("cp.async.cg.shared.global [%0], [%1], 16;" ::
                         "r"(dst), "l"(src));
        }
        asm volatile("cp.async.commit_group;");
    };

    load_tile(0, 0);

    const int ntiles = K / BK;
    for (int it = 0; it < ntiles; it++) {
        int cur = it & 1;
        bool has_next = (it + 1) < ntiles;
        if (has_next) load_tile(cur ^ 1, (it + 1) * BK);

        if (has_next) asm volatile("cp.async.wait_group 1;");
        else          asm volatile("cp.async.wait_group 0;");
        __syncthreads();

#pragma unroll
        for (int ks = 0; ks < BK; ks += 8) {
            unsigned af[MT][4];
            unsigned bf[NT][2];
#pragma unroll
            for (int mt = 0; mt < MT; mt++) {
                int r0 = wm * WM + mt * 16 + g;
                af[mt][0] = f2tf32(As[cur][r0    ][ks + t4]);
                af[mt][1] = f2tf32(As[cur][r0 + 8][ks + t4]);
                af[mt][2] = f2tf32(As[cur][r0    ][ks + t4 + 4]);
                af[mt][3] = f2tf32(As[cur][r0 + 8][ks + t4 + 4]);
            }
#pragma unroll
            for (int nt = 0; nt < NT; nt++) {
                int c0 = wn * WN + nt * 8 + g;
                bf[nt][0] = f2tf32(Bs[cur][ks + t4    ][c0]);
                bf[nt][1] = f2tf32(Bs[cur][ks + t4 + 4][c0]);
            }
#pragma unroll
            for (int mt = 0; mt < MT; mt++)
#pragma unroll
                for (int nt = 0; nt < NT; nt++) {
                    asm volatile(
                        "mma.sync.aligned.m16n8k8.row.col.f32.tf32.tf32.f32 "
                        "{%0,%1,%2,%3}, {%4,%5,%6,%7}, {%8,%9}, {%0,%1,%2,%3};"
                        : "+f"(acc[mt][nt][0]), "+f"(acc[mt][nt][1]),
                          "+f"(acc[mt][nt][2]), "+f"(acc[mt][nt][3])
                        : "r"(af[mt][0]), "r"(af[mt][1]),
                          "r"(af[mt][2]), "r"(af[mt][3]),
                          "r"(bf[nt][0]), "r"(bf[nt][1]));
                }
        }
        __syncthreads();
    }

    // epilogue
#pragma unroll
    for (int mt = 0; mt < MT; mt++) {
#pragma unroll
        for (int nt = 0; nt < NT; nt++) {
            int r = bm0 + wm * WM + mt * 16 + g;
            int c = bn0 + wn * WN + nt * 8 + 2 * t4;
            C[(size_t)r * ldc + c]           = acc[mt][nt][0];
            C[(size_t)r * ldc + c + 1]       = acc[mt][nt][1];
            C[(size_t)(r + 8) * ldc + c]     = acc[mt][nt][2];
            C[(size_t)(r + 8) * ldc + c + 1] = acc[mt][nt][3];
        }
    }
}

// ---------------------------------------------------------------------------
// Causal depthwise conv (k=4) + bias + SiLU, writes forward + reversed copies
// ---------------------------------------------------------------------------
__global__ void conv_silu_kernel(const float* __restrict__ xz,
                                 const float* __restrict__ cw,
                                 const float* __restrict__ cb,
                                 float* __restrict__ xs) {
    int idx = blockIdx.x * blockDim.x + threadIdx.x;  // over (BN, L, DI)
    if (idx >= BB * NN * LL * DI) return;
    int d = idx % DI;
    int t = (idx / DI) % LL;
    int bn = idx / (DI * LL);          // b*NN + n
    int b = bn / NN, n = bn % NN;

    float w0 = cw[d * DC + 0], w1 = cw[d * DC + 1];
    float w2 = cw[d * DC + 2], w3 = cw[d * DC + 3];

    const float* xr = xz + ((size_t)bn * LL) * O_IN + d;  // x half: cols [0,512)
    float acc = cb[d];
    if (t - 3 >= 0) acc += xr[(size_t)(t - 3) * O_IN] * w0;
    if (t - 2 >= 0) acc += xr[(size_t)(t - 2) * O_IN] * w1;
    if (t - 1 >= 0) acc += xr[(size_t)(t - 1) * O_IN] * w2;
    acc += xr[(size_t)t * O_IN] * w3;
    float v = silu_f(acc);

    xs[((size_t)((b * KK + n) * LL + t)) * DI + d] = v;
    xs[((size_t)((b * KK + 2 + n) * LL + (LL - 1 - t))) * DI + d] = v;
}

// ---------------------------------------------------------------------------
// dt_w transpose (512x32 -> 32x512)
// ---------------------------------------------------------------------------
__global__ void transpose_dtw(const float* __restrict__ dtw, float* __restrict__ out) {
    int idx = blockIdx.x * blockDim.x + threadIdx.x;
    if (idx >= DTR * DI) return;
    int d = idx % DI, j = idx / DI;
    out[j * DI + d] = dtw[d * DTR + j];
}

// ---------------------------------------------------------------------------
// delta = softplus(dts + dt_bias[k]) in place
// ---------------------------------------------------------------------------
__global__ void softplus_bias_kernel(float* __restrict__ delta,
                                     const float* __restrict__ dt_bias) {
    int idx = blockIdx.x * blockDim.x + threadIdx.x;
    if (idx >= M_XS * DI) return;
    int d = idx % DI;
    int r = idx / DI;            // r = (b*4 + k)*L + t
    int k = (r / LL) % KK;
    delta[idx] = softplus_f(delta[idx] + dt_bias[k * DI + d]);
}

// ---------------------------------------------------------------------------
// Selective scan. Block = (b,k,dblk of 128). 512 threads = 128 d x 4 state-
// groups (4 states each). Quad shuffle-reduce for y = sum_n h_n C_n.
// ---------------------------------------------------------------------------
__global__ __launch_bounds__(512)
void scan_kernel(const float* __restrict__ xs,
                 const float* __restrict__ delta,
                 const float* __restrict__ xdbl,
                 const float* __restrict__ A_logs,
                 const float* __restrict__ Ds,
                 float* __restrict__ y) {
    int bk   = blockIdx.x >> 2;          // b*4 + k  (0..7)
    int dblk = blockIdx.x & 3;
    int tid  = threadIdx.x;
    int dl_  = tid >> 2;                 // 0..127
    int ng   = tid & 3;                  // state group
    int d    = dblk * 128 + dl_;
    int kdir = bk & 3;

    float A[4], h[4];
#pragma unroll
    for (int j = 0; j < 4; j++) {
        A[j] = -expf(A_logs[((size_t)(kdir * DI + d)) * DS + ng * 4 + j]);
        h[j] = 0.0f;
    }
    float Dv = Ds[kdir * DI + d];

    const size_t rowbase = (size_t)bk * LL;
    for (int t = 0; t < LL; t++) {
        size_t r = rowbase + t;
        float dl = delta[r * DI + d];
        float u  = xs[r * DI + d];
        float du = dl * u;
        const float* Bp = xdbl + r * O_X + DTR + ng * 4;
        const float* Cp = Bp + DS;
        float cy = 0.0f;
#pragma unroll
        for (int j = 0; j < 4; j++) {
            float e = __expf(dl * A[j]);
            h[j] = h[j] * e + du * __ldg(&Bp[j]);
            cy += h[j] * __ldg(&Cp[j]);
        }
        cy += __shfl_xor_sync(0xffffffffu, cy, 1);
        cy += __shfl_xor_sync(0xffffffffu, cy, 2);
        if (ng == 0) y[r * DI + d] = cy + u * Dv;
    }
}

// ---------------------------------------------------------------------------
// Merge fwd/bwd scans and concat with z: g_cat (B,2,L,1024)
// ---------------------------------------------------------------------------
__global__ void merge_kernel(const float* __restrict__ y,
                             const float* __restrict__ xz,
                             float* __restrict__ cat) {
    int idx = blockIdx.x * blockDim.x + threadIdx.x;  // over (B,N,L,DI)
    if (idx >= BB * NN * LL * DI) return;
    int d = idx % DI;
    int t = (idx / DI) % LL;
    int bn = idx / (DI * LL);
    int b = bn / NN, n = bn % NN;

    float yf = y[((size_t)((b * KK + n) * LL + t)) * DI + d];
    float yb = y[((size_t)((b * KK + 2 + n) * LL + (LL - 1 - t))) * DI + d];
    size_t row = (size_t)bn * LL + t;
    cat[row * O_IN + d]        = yf + yb;
    cat[row * O_IN + DI + d]   = xz[row * O_IN + DI + d];
}

// ---------------------------------------------------------------------------
// Launch
// ---------------------------------------------------------------------------
static inline int cdiv(int a, int b) { return (a + b - 1) / b; }

extern "C" void kernel_launch(void* const* d_in, const int* in_sizes, int n_in,
                              void* d_out, int out_size) {
    const float* hs      = (const float*)d_in[0];
    const float* in_bw   = (const float*)d_in[1];
    const float* in_sw   = (const float*)d_in[2];
    const float* in_sc   = (const float*)d_in[3];
    const float* conv_w  = (const float*)d_in[4];
    const float* conv_b  = (const float*)d_in[5];
    const float* x_bw    = (const float*)d_in[6];
    const float* x_sw    = (const float*)d_in[7];
    const float* x_sc    = (const float*)d_in[8];
    const float* dt_w    = (const float*)d_in[9];
    const float* dt_bias = (const float*)d_in[10];
    const float* A_logs  = (const float*)d_in[11];
    const float* Ds      = (const float*)d_in[12];
    const float* out_bw  = (const float*)d_in[13];
    const float* out_sw  = (const float*)d_in[14];
    const float* out_sc  = (const float*)d_in[15];
    float* out = (float*)d_out;

    float *F, *Wc, *Wcx, *xz, *xs, *xdbl, *delta, *yb, *cat, *dtwT;
    cudaGetSymbolAddress((void**)&F,     g_F);
    cudaGetSymbolAddress((void**)&Wc,    g_Wc);
    cudaGetSymbolAddress((void**)&Wcx,   g_Wcx);
    cudaGetSymbolAddress((void**)&xz,    g_xz);
    cudaGetSymbolAddress((void**)&xs,    g_xs);
    cudaGetSymbolAddress((void**)&xdbl,  g_xdbl);
    cudaGetSymbolAddress((void**)&delta, g_delta);
    cudaGetSymbolAddress((void**)&yb,    g_y);
    cudaGetSymbolAddress((void**)&cat,   g_cat);
    cudaGetSymbolAddress((void**)&dtwT,  g_dtwT);

    const int TPB = 256;

    // ---- in-proj KAN: xz = KAN(hidden_states) ----
    prep_weights<<<cdiv(O_IN * DM, TPB), TPB>>>(in_bw, in_sw, in_sc, Wc, O_IN, DM);
    features_kernel<<<cdiv(M_IN * DM, TPB), TPB>>>(hs, F, M_IN, DM);
    {
        dim3 grid(O_IN / 128, M_IN / 128);
        tf32_gemm<128, 128, 16, 2, 4><<<grid, 256>>>(F, Wc, xz, M_IN, O_IN, K_IN,
                                                     K_IN, O_IN, O_IN);
    }

    // ---- conv + silu -> xs (fwd + reversed) ----
    conv_silu_kernel<<<cdiv(BB * NN * LL * DI, TPB), TPB>>>(xz, conv_w, conv_b, xs);

    // ---- x-proj KAN: x_dbl = KAN(xs) ----
    prep_weights<<<cdiv(O_X * DI, TPB), TPB>>>(x_bw, x_sw, x_sc, Wcx, O_X, DI);
    features_kernel<<<cdiv(M_XS * DI, TPB), TPB>>>(xs, F, M_XS, DI);
    {
        dim3 grid(O_X / 64, M_XS / 64);
        tf32_gemm<64, 64, 16, 2, 4><<<grid, 256>>>(F, Wcx, xdbl, M_XS, O_X, K_IN,
                                                   K_IN, O_X, O_X);
    }

    // ---- dts = dt @ dt_w^T ; delta = softplus(dts + bias) ----
    transpose_dtw<<<cdiv(DTR * DI, TPB), TPB>>>(dt_w, dtwT);
    {
        dim3 grid(DI / 128, M_XS / 128);
        tf32_gemm<128, 128, 16, 2, 4><<<grid, 256>>>(xdbl, dtwT, delta, M_XS, DI, DTR,
                                                     O_X, DI, DI);
    }
    softplus_bias_kernel<<<cdiv(M_XS * DI, TPB), TPB>>>(delta, dt_bias);

    // ---- selective scan (+ u*D) ----
    scan_kernel<<<32, 512>>>(xs, delta, xdbl, A_logs, Ds, yb);

    // ---- merge fwd/bwd, concat z ----
    merge_kernel<<<cdiv(BB * NN * LL * DI, TPB), TPB>>>(yb, xz, cat);

    // ---- out-proj KAN: out = KAN(cat) ----
    prep_weights<<<cdiv(O_OUT * O_IN, TPB), TPB>>>(out_bw, out_sw, out_sc, Wc, O_OUT, O_IN);
    features_kernel<<<cdiv(M_IN * O_IN, TPB), TPB>>>(cat, F, M_IN, O_IN);
    {
        dim3 grid(O_OUT / 128, M_IN / 128);
        tf32_gemm<128, 128, 16, 2, 4><<<grid, 256>>>(F, Wc, out, M_IN, O_OUT, K_OUT,
                                                     K_OUT, O_OUT, O_OUT);
    }
}